// round 3
// baseline (speedup 1.0000x reference)
#include <cuda_runtime.h>
#include <cuda_bf16.h>
#include <math.h>

#define NTOK 4096
#define DDIM 1024
#define NEXP 8
#define CAP  1280
#define NASSIGN (2 * NTOK)          // 8192 (k-major: p = k*NTOK + n)
#define NSLOT (NEXP * CAP)          // 10240
#define ROW   (NEXP * CAP)          // 10240 floats per token row in W / M

// Output layout (fp32, concatenated in reference return order)
#define W_OFF 0ULL
#define M_OFF 41943040ULL
#define B_OFF 83886080ULL
#define L_OFF 94371840ULL

// Scratch (device globals; no allocations allowed)
__device__ int   g_topi[NTOK * 2];
__device__ float g_topp[NTOK * 2];
__device__ int   g_rank[NASSIGN];   // indexed by p = k*NTOK + n
__device__ int   g_slot[NSLOT];

// ---------------------------------------------------------------------------
// 1) Fused router logits + top-2 + softmax. One warp per token; w_gate in
//    smem. After the xor butterfly every lane holds all 8 sums.
// ---------------------------------------------------------------------------
__global__ void logits_top2_kernel(const float* __restrict__ x,
                                   const float* __restrict__ w,
                                   float* __restrict__ out)
{
    __shared__ float sw[NEXP * DDIM];          // 32 KB
    for (int i = threadIdx.x; i < NEXP * DDIM; i += blockDim.x)
        sw[i] = w[i];
    __syncthreads();

    const int warp = threadIdx.x >> 5;
    const int lane = threadIdx.x & 31;
    const int n = blockIdx.x * (blockDim.x >> 5) + warp;   // token
    if (n >= NTOK) return;

    const float* xr = x + (size_t)n * DDIM;
    float acc[NEXP];
    #pragma unroll
    for (int e = 0; e < NEXP; e++) acc[e] = 0.f;

    #pragma unroll 4
    for (int d = lane; d < DDIM; d += 32) {
        float xv = xr[d];
        #pragma unroll
        for (int e = 0; e < NEXP; e++)
            acc[e] = fmaf(xv, sw[e * DDIM + d], acc[e]);
    }
    #pragma unroll
    for (int off = 16; off > 0; off >>= 1) {
        #pragma unroll
        for (int e = 0; e < NEXP; e++)
            acc[e] += __shfl_xor_sync(0xffffffffu, acc[e], off);
    }
    if (lane < NEXP)
        out[L_OFF + (size_t)n * NEXP + lane] = acc[lane];

    if (lane == 0) {
        int i0 = 0; float b0 = acc[0];
        #pragma unroll
        for (int e = 1; e < NEXP; e++)
            if (acc[e] > b0) { b0 = acc[e]; i0 = e; }
        int i1 = -1; float b1 = -INFINITY;
        #pragma unroll
        for (int e = 0; e < NEXP; e++)
            if (e != i0 && acc[e] > b1) { b1 = acc[e]; i1 = e; }
        float e1 = __expf(b1 - b0);
        float inv = 1.0f / (1.0f + e1);
        g_topi[n * 2 + 0] = i0;
        g_topi[n * 2 + 1] = i1;
        g_topp[n * 2 + 0] = inv;
        g_topp[n * 2 + 1] = e1 * inv;
    }
}

// ---------------------------------------------------------------------------
// 2) Fused rank + slot map. One block per expert. Deterministic k-major
//    exclusive prefix scan over the 8192 assignment positions. Block e
//    exclusively owns slot range [e*CAP, (e+1)*CAP): it initializes it to -1
//    and writes slot[r] = n for its own kept assignments. No cross-block
//    hazards, no separate scatter kernel.
// ---------------------------------------------------------------------------
__global__ void rank_slot_kernel()
{
    const int e = blockIdx.x;           // expert
    const int t = threadIdx.x;          // 1024 threads
    const int PER = NASSIGN / 1024;     // 8 positions per thread

    // init this expert's own slot range
    if (t < CAP) g_slot[e * CAP + t] = -1;
    if (t + 1024 < CAP) g_slot[e * CAP + t + 1024] = -1;

    int flag[8];
    int local[8];
    int cnt = 0;
    #pragma unroll
    for (int i = 0; i < PER; i++) {
        int p = t * PER + i;
        int k = p >> 12;                // p / NTOK
        int n = p & (NTOK - 1);         // p % NTOK
        int ex = g_topi[n * 2 + k];
        flag[i] = (ex == e);
        local[i] = cnt;
        cnt += flag[i];
    }

    __shared__ int s[1024];
    s[t] = cnt;
    __syncthreads();
    #pragma unroll
    for (int off = 1; off < 1024; off <<= 1) {
        int vv = (t >= off) ? s[t - off] : 0;
        __syncthreads();
        s[t] += vv;
        __syncthreads();
    }
    int excl = s[t] - cnt;

    #pragma unroll
    for (int i = 0; i < PER; i++) {
        if (flag[i]) {
            int p = t * PER + i;
            int r = excl + local[i];
            g_rank[p] = r;
            if (r < CAP) {
                int n = p & (NTOK - 1);
                g_slot[e * CAP + r] = n;   // own range only (init'd above, same block)
            }
        }
    }
}

// ---------------------------------------------------------------------------
// 3) Single store-bound wave:
//    blocks [0, NTOK):           token n's full W row + M row (zeros with the
//                                <=2 nonzeros folded in; fill+scatter fused)
//    blocks [NTOK, NTOK+NSLOT):  expert_batches slot copy (x row or zeros)
// ---------------------------------------------------------------------------
__global__ void big_write_kernel(const float* __restrict__ x,
                                 float* __restrict__ out)
{
    const int b = blockIdx.x;
    const int t = threadIdx.x;

    if (b < NTOK) {
        const int n = b;
        // nonzero positions for this token's row
        int e0 = g_topi[n * 2 + 0];
        int e1 = g_topi[n * 2 + 1];
        int r0 = g_rank[n];             // p = 0*NTOK + n
        int r1 = g_rank[NTOK + n];      // p = 1*NTOK + n
        float w0 = g_topp[n * 2 + 0];
        float w1 = g_topp[n * 2 + 1];
        int q0 = (r0 < CAP) ? (e0 * CAP + r0) : -1;   // float index in row
        int q1 = (r1 < CAP) ? (e1 * CAP + r1) : -1;
        int c0 = q0 >> 2, l0 = q0 & 3;
        int c1 = q1 >> 2, l1 = q1 & 3;

        float4* wrow = reinterpret_cast<float4*>(out + W_OFF + (size_t)n * ROW);
        float4* mrow = reinterpret_cast<float4*>(out + M_OFF + (size_t)n * ROW);

        const int NCHUNK = ROW / 4;     // 2560 float4s per row
        #pragma unroll
        for (int j = 0; j < NCHUNK / 256; j++) {     // 10 iterations
            int c = t + j * 256;
            float4 vw = make_float4(0.f, 0.f, 0.f, 0.f);
            float4 vm = make_float4(0.f, 0.f, 0.f, 0.f);
            if (c == c0 && q0 >= 0) {
                reinterpret_cast<float*>(&vw)[l0] = w0;
                reinterpret_cast<float*>(&vm)[l0] = 1.0f;
            }
            if (c == c1 && q1 >= 0) {
                reinterpret_cast<float*>(&vw)[l1] = w1;
                reinterpret_cast<float*>(&vm)[l1] = 1.0f;
            }
            wrow[c] = vw;
            mrow[c] = vm;
        }
    } else {
        const int slot = b - NTOK;      // 0..NSLOT-1
        int n = g_slot[slot];
        float4* dst = reinterpret_cast<float4*>(out + B_OFF + (size_t)slot * DDIM);
        if (n >= 0) {
            const float4* src = reinterpret_cast<const float4*>(x + (size_t)n * DDIM);
            dst[t] = src[t];
        } else {
            dst[t] = make_float4(0.f, 0.f, 0.f, 0.f);
        }
    }
}

extern "C" void kernel_launch(void* const* d_in, const int* in_sizes, int n_in,
                              void* d_out, int out_size)
{
    const float* x = (const float*)d_in[0];       // [2,2048,1024]
    const float* w = (const float*)d_in[1];       // [8,1024]
    float* out = (float*)d_out;

    logits_top2_kernel<<<512, 256>>>(x, w, out);
    rank_slot_kernel<<<NEXP, 1024>>>();
    big_write_kernel<<<NTOK + NSLOT, 256>>>(x, out);
}

// round 4
// speedup vs baseline: 1.4155x; 1.4155x over previous
#include <cuda_runtime.h>
#include <cuda_bf16.h>
#include <math.h>

#define NTOK 4096
#define DDIM 1024
#define NEXP 8
#define CAP  1280
#define NASSIGN (2 * NTOK)          // 8192 (k-major: p = k*NTOK + n)
#define NSLOT (NEXP * CAP)          // 10240

// Output layout (fp32, concatenated in reference return order)
#define W_OFF 0ULL
#define M_OFF 41943040ULL
#define B_OFF 83886080ULL
#define L_OFF 94371840ULL
#define WM_FLOATS 83886080ULL       // W + M regions (contiguous) to zero

// Scratch (device globals; no allocations allowed)
__device__ int   g_topi[NTOK * 2];
__device__ float g_topp[NTOK * 2];
__device__ int   g_rank[NASSIGN];   // indexed by p = k*NTOK + n
__device__ int   g_slot[NSLOT];

// Side stream/events for graph fork-join (created pre-main; no device mem alloc)
static cudaStream_t g_s1;
static cudaEvent_t  g_evFork, g_evJoin;
namespace {
struct StreamInit {
    StreamInit() {
        cudaStreamCreateWithFlags(&g_s1, cudaStreamNonBlocking);
        cudaEventCreateWithFlags(&g_evFork, cudaEventDisableTiming);
        cudaEventCreateWithFlags(&g_evJoin, cudaEventDisableTiming);
    }
} g_streamInit;
}

// ---------------------------------------------------------------------------
// 1) Fused router logits + top-2 + softmax. One warp per token. All memory
//    traffic vectorized to float4: 8 LDG.128 + 64 LDS.128 per lane.
// ---------------------------------------------------------------------------
__global__ void logits_top2_kernel(const float* __restrict__ x,
                                   const float* __restrict__ w,
                                   float* __restrict__ out)
{
    __shared__ float4 sw4[NEXP * 256];          // 32 KB, [e][d4]
    {
        const float4* w4 = reinterpret_cast<const float4*>(w);
        for (int i = threadIdx.x; i < NEXP * 256; i += blockDim.x)
            sw4[i] = w4[i];
    }
    __syncthreads();

    const int warp = threadIdx.x >> 5;
    const int lane = threadIdx.x & 31;
    const int n = blockIdx.x * (blockDim.x >> 5) + warp;   // token
    if (n >= NTOK) return;

    const float4* xr4 = reinterpret_cast<const float4*>(x + (size_t)n * DDIM);
    float acc[NEXP];
    #pragma unroll
    for (int e = 0; e < NEXP; e++) acc[e] = 0.f;

    #pragma unroll
    for (int i = 0; i < 8; i++) {               // 256 float4s / 32 lanes
        const int d4 = i * 32 + lane;
        float4 xv = xr4[d4];
        #pragma unroll
        for (int e = 0; e < NEXP; e++) {
            float4 wv = sw4[e * 256 + d4];
            acc[e] = fmaf(xv.x, wv.x, acc[e]);
            acc[e] = fmaf(xv.y, wv.y, acc[e]);
            acc[e] = fmaf(xv.z, wv.z, acc[e]);
            acc[e] = fmaf(xv.w, wv.w, acc[e]);
        }
    }
    #pragma unroll
    for (int off = 16; off > 0; off >>= 1) {
        #pragma unroll
        for (int e = 0; e < NEXP; e++)
            acc[e] += __shfl_xor_sync(0xffffffffu, acc[e], off);
    }
    if (lane < NEXP)
        out[L_OFF + (size_t)n * NEXP + lane] = acc[lane];

    if (lane == 0) {
        int i0 = 0; float b0 = acc[0];
        #pragma unroll
        for (int e = 1; e < NEXP; e++)
            if (acc[e] > b0) { b0 = acc[e]; i0 = e; }
        int i1 = -1; float b1 = -INFINITY;
        #pragma unroll
        for (int e = 0; e < NEXP; e++)
            if (e != i0 && acc[e] > b1) { b1 = acc[e]; i1 = e; }
        float e1 = __expf(b1 - b0);
        float inv = 1.0f / (1.0f + e1);
        g_topi[n * 2 + 0] = i0;
        g_topi[n * 2 + 1] = i1;
        g_topp[n * 2 + 0] = inv;
        g_topp[n * 2 + 1] = e1 * inv;
    }
}

// ---------------------------------------------------------------------------
// 2) Fused rank + slot map. One block per expert; deterministic k-major
//    exclusive prefix scan. Block e exclusively owns slots [e*CAP,(e+1)*CAP):
//    inits them to -1 and writes slot[r]=n for kept assignments.
// ---------------------------------------------------------------------------
__global__ void rank_slot_kernel()
{
    const int e = blockIdx.x;           // expert
    const int t = threadIdx.x;          // 1024 threads
    const int PER = NASSIGN / 1024;     // 8 positions per thread

    if (t < CAP) g_slot[e * CAP + t] = -1;
    if (t + 1024 < CAP) g_slot[e * CAP + t + 1024] = -1;

    int flag[8];
    int local[8];
    int cnt = 0;
    #pragma unroll
    for (int i = 0; i < PER; i++) {
        int p = t * PER + i;
        int k = p >> 12;                // p / NTOK
        int n = p & (NTOK - 1);         // p % NTOK
        int ex = g_topi[n * 2 + k];
        flag[i] = (ex == e);
        local[i] = cnt;
        cnt += flag[i];
    }

    __shared__ int s[1024];
    s[t] = cnt;
    __syncthreads();
    #pragma unroll
    for (int off = 1; off < 1024; off <<= 1) {
        int vv = (t >= off) ? s[t - off] : 0;
        __syncthreads();
        s[t] += vv;
        __syncthreads();
    }
    int excl = s[t] - cnt;

    #pragma unroll
    for (int i = 0; i < PER; i++) {
        if (flag[i]) {
            int p = t * PER + i;
            int r = excl + local[i];
            g_rank[p] = r;
            if (r < CAP) {
                int n = p & (NTOK - 1);
                g_slot[e * CAP + r] = n;
            }
        }
    }
}

// ---------------------------------------------------------------------------
// 3) expert_batches: slot (e,c) = verbatim x-row copy or zeros.
// ---------------------------------------------------------------------------
__global__ void gather_kernel(const float* __restrict__ x,
                              float* __restrict__ out)
{
    int slot = blockIdx.x;              // 0..NSLOT-1
    int n = g_slot[slot];
    float4* dst = reinterpret_cast<float4*>(out + B_OFF + (size_t)slot * DDIM);
    if (n >= 0) {
        const float4* src = reinterpret_cast<const float4*>(x + (size_t)n * DDIM);
        dst[threadIdx.x] = src[threadIdx.x];
    } else {
        dst[threadIdx.x] = make_float4(0.f, 0.f, 0.f, 0.f);
    }
}

// ---------------------------------------------------------------------------
// 4) Sparse W/M scatter over the zeroed regions (after memset joins).
// ---------------------------------------------------------------------------
__global__ void scatter_wm_kernel(float* __restrict__ out)
{
    int p = blockIdx.x * blockDim.x + threadIdx.x;
    if (p >= NASSIGN) return;
    int k = p >> 12;
    int n = p & (NTOK - 1);
    int e = g_topi[n * 2 + k];
    int r = g_rank[p];
    if (r < CAP) {
        float pr = g_topp[n * 2 + k];
        size_t idx = (size_t)n * (NEXP * CAP) + (size_t)e * CAP + r;
        out[W_OFF + idx] = pr;
        out[M_OFF + idx] = 1.0f;
    }
}

extern "C" void kernel_launch(void* const* d_in, const int* in_sizes, int n_in,
                              void* d_out, int out_size)
{
    const float* x = (const float*)d_in[0];       // [2,2048,1024]
    const float* w = (const float*)d_in[1];       // [8,1024]
    float* out = (float*)d_out;

    // Fork: zero W+M (contiguous 335.5 MB) on side stream via memset node.
    cudaEventRecord(g_evFork, 0);
    cudaStreamWaitEvent(g_s1, g_evFork, 0);
    cudaMemsetAsync(out, 0, WM_FLOATS * sizeof(float), g_s1);

    // Main chain (doesn't touch W/M until the join).
    logits_top2_kernel<<<512, 256>>>(x, w, out);
    rank_slot_kernel<<<NEXP, 1024>>>();
    gather_kernel<<<NSLOT, 256>>>(x, out);

    // Join: sparse W/M writes need the zeroed regions.
    cudaEventRecord(g_evJoin, g_s1);
    cudaStreamWaitEvent(0, g_evJoin, 0);
    scatter_wm_kernel<<<(NASSIGN + 255) / 256, 256>>>(out);
}

// round 5
// speedup vs baseline: 1.4528x; 1.0263x over previous
#include <cuda_runtime.h>
#include <cuda_bf16.h>
#include <math.h>

#define NTOK 4096
#define DDIM 1024
#define NEXP 8
#define CAP  1280
#define NASSIGN (2 * NTOK)          // 8192 (k-major: p = k*NTOK + n)
#define NSLOT (NEXP * CAP)          // 10240
#define ROWF  (NEXP * CAP)          // 10240 floats per token row

// Output layout (fp32, concatenated in reference return order)
#define W_OFF 0ULL
#define M_OFF 41943040ULL
#define B_OFF 83886080ULL
#define L_OFF 94371840ULL

// Fill chunking: 4 chunks = W tokens [0,2048), W [2048,4096), M [0,2048), M [2048,4096)
#define HALF_FLOATS (2048ULL * ROWF)            // 20,971,520 floats per half-region
#define HALF_VEC4   (HALF_FLOATS / 4)           // 5,242,880 float4

// Scratch (device globals; no allocations allowed)
__device__ int   g_topi[NTOK * 2];
__device__ float g_topp[NTOK * 2];
__device__ int   g_sidx[NASSIGN];   // flat idx into W region (or -1), p = k*NTOK+n
__device__ float g_sw[NASSIGN];     // weight for that entry
__device__ int   g_slot[NSLOT];

static cudaStream_t g_s1;
static cudaEvent_t  g_evFork, g_ev[4];
namespace {
struct StreamInit {
    StreamInit() {
        cudaStreamCreateWithFlags(&g_s1, cudaStreamNonBlocking);
        cudaEventCreateWithFlags(&g_evFork, cudaEventDisableTiming);
        for (int i = 0; i < 4; i++)
            cudaEventCreateWithFlags(&g_ev[i], cudaEventDisableTiming);
    }
} g_streamInit;
}

// ---------------------------------------------------------------------------
// 1) Fused router logits + top-2 + softmax. One warp per token, float4 I/O.
// ---------------------------------------------------------------------------
__global__ void logits_top2_kernel(const float* __restrict__ x,
                                   const float* __restrict__ w,
                                   float* __restrict__ out)
{
    __shared__ float4 sw4[NEXP * 256];          // 32 KB, [e][d4]
    {
        const float4* w4 = reinterpret_cast<const float4*>(w);
        for (int i = threadIdx.x; i < NEXP * 256; i += blockDim.x)
            sw4[i] = w4[i];
    }
    __syncthreads();

    const int warp = threadIdx.x >> 5;
    const int lane = threadIdx.x & 31;
    const int n = blockIdx.x * (blockDim.x >> 5) + warp;   // token
    if (n >= NTOK) return;

    const float4* xr4 = reinterpret_cast<const float4*>(x + (size_t)n * DDIM);
    float acc[NEXP];
    #pragma unroll
    for (int e = 0; e < NEXP; e++) acc[e] = 0.f;

    #pragma unroll
    for (int i = 0; i < 8; i++) {
        const int d4 = i * 32 + lane;
        float4 xv = xr4[d4];
        #pragma unroll
        for (int e = 0; e < NEXP; e++) {
            float4 wv = sw4[e * 256 + d4];
            acc[e] = fmaf(xv.x, wv.x, acc[e]);
            acc[e] = fmaf(xv.y, wv.y, acc[e]);
            acc[e] = fmaf(xv.z, wv.z, acc[e]);
            acc[e] = fmaf(xv.w, wv.w, acc[e]);
        }
    }
    #pragma unroll
    for (int off = 16; off > 0; off >>= 1) {
        #pragma unroll
        for (int e = 0; e < NEXP; e++)
            acc[e] += __shfl_xor_sync(0xffffffffu, acc[e], off);
    }
    if (lane < NEXP)
        out[L_OFF + (size_t)n * NEXP + lane] = acc[lane];

    if (lane == 0) {
        int i0 = 0; float b0 = acc[0];
        #pragma unroll
        for (int e = 1; e < NEXP; e++)
            if (acc[e] > b0) { b0 = acc[e]; i0 = e; }
        int i1 = -1; float b1 = -INFINITY;
        #pragma unroll
        for (int e = 0; e < NEXP; e++)
            if (e != i0 && acc[e] > b1) { b1 = acc[e]; i1 = e; }
        float e1 = __expf(b1 - b0);
        float inv = 1.0f / (1.0f + e1);
        g_topi[n * 2 + 0] = i0;
        g_topi[n * 2 + 1] = i1;
        g_topp[n * 2 + 0] = inv;
        g_topp[n * 2 + 1] = e1 * inv;
    }
}

// ---------------------------------------------------------------------------
// 2) Fused rank + slot map + packed scatter list. One block per expert;
//    deterministic k-major exclusive scan. Emits for each assignment p the
//    flat W-region index (or -1) and its weight, so later scatters are
//    1 load + 1 store.
// ---------------------------------------------------------------------------
__global__ void rank_slot_kernel()
{
    const int e = blockIdx.x;           // expert
    const int t = threadIdx.x;          // 1024 threads
    const int PER = NASSIGN / 1024;     // 8 positions per thread

    if (t < CAP) g_slot[e * CAP + t] = -1;
    if (t + 1024 < CAP) g_slot[e * CAP + t + 1024] = -1;

    int flag[8];
    int local[8];
    int cnt = 0;
    #pragma unroll
    for (int i = 0; i < PER; i++) {
        int p = t * PER + i;
        int k = p >> 12;
        int n = p & (NTOK - 1);
        int ex = g_topi[n * 2 + k];
        flag[i] = (ex == e);
        local[i] = cnt;
        cnt += flag[i];
    }

    __shared__ int s[1024];
    s[t] = cnt;
    __syncthreads();
    #pragma unroll
    for (int off = 1; off < 1024; off <<= 1) {
        int vv = (t >= off) ? s[t - off] : 0;
        __syncthreads();
        s[t] += vv;
        __syncthreads();
    }
    int excl = s[t] - cnt;

    #pragma unroll
    for (int i = 0; i < PER; i++) {
        if (flag[i]) {
            int p = t * PER + i;
            int k = p >> 12;
            int n = p & (NTOK - 1);
            int r = excl + local[i];
            if (r < CAP) {
                g_sidx[p] = n * ROWF + e * CAP + r;
                g_sw[p]   = g_topp[n * 2 + k];
                g_slot[e * CAP + r] = n;
            } else {
                g_sidx[p] = -1;
            }
        }
    }
}

// ---------------------------------------------------------------------------
// 3) expert_batches: slot (e,c) = verbatim x-row copy or zeros.
//    Streaming stores; x reads should hit L2 (kept warm by evict-first fills).
// ---------------------------------------------------------------------------
__global__ void gather_kernel(const float* __restrict__ x,
                              float* __restrict__ out)
{
    int slot = blockIdx.x;              // 0..NSLOT-1
    int n = g_slot[slot];
    float4* dst = reinterpret_cast<float4*>(out + B_OFF + (size_t)slot * DDIM);
    if (n >= 0) {
        const float4* src = reinterpret_cast<const float4*>(x + (size_t)n * DDIM);
        __stcs(dst + threadIdx.x, src[threadIdx.x]);
    } else {
        __stcs(dst + threadIdx.x, make_float4(0.f, 0.f, 0.f, 0.f));
    }
}

// ---------------------------------------------------------------------------
// 4) Chunked zero-fill with evict-first streaming stores (doesn't evict x).
//    base points at the start of a half-region (HALF_VEC4 float4s).
// ---------------------------------------------------------------------------
__global__ void fill_cs_kernel(float4* __restrict__ base)
{
    const float4 z = make_float4(0.f, 0.f, 0.f, 0.f);
    size_t stride = (size_t)gridDim.x * blockDim.x;
    for (size_t c = (size_t)blockIdx.x * blockDim.x + threadIdx.x;
         c < HALF_VEC4; c += stride)
        __stcs(base + c, z);
}

// ---------------------------------------------------------------------------
// 5) Sparse scatters per token-half: weights-only / mask-only.
//    4096 entries each: t -> k = t>>11, n = n0 + (t & 2047).
// ---------------------------------------------------------------------------
__global__ void scatter_w_kernel(float* __restrict__ out, int n0)
{
    int t = blockIdx.x * blockDim.x + threadIdx.x;
    if (t >= 2 * 2048) return;
    int p = (t >> 11) * NTOK + n0 + (t & 2047);
    int idx = g_sidx[p];
    if (idx >= 0) out[W_OFF + (size_t)idx] = g_sw[p];
}

__global__ void scatter_m_kernel(float* __restrict__ out, int n0)
{
    int t = blockIdx.x * blockDim.x + threadIdx.x;
    if (t >= 2 * 2048) return;
    int p = (t >> 11) * NTOK + n0 + (t & 2047);
    int idx = g_sidx[p];
    if (idx >= 0) out[M_OFF + (size_t)idx] = 1.0f;
}

extern "C" void kernel_launch(void* const* d_in, const int* in_sizes, int n_in,
                              void* d_out, int out_size)
{
    const float* x = (const float*)d_in[0];       // [2,2048,1024]
    const float* w = (const float*)d_in[1];       // [8,1024]
    float* out = (float*)d_out;
    float4* out4 = (float4*)d_out;

    // Fork: chunked zero-fill of W then M (half-regions) on side stream.
    cudaEventRecord(g_evFork, 0);
    cudaStreamWaitEvent(g_s1, g_evFork, 0);
    fill_cs_kernel<<<4096, 256, 0, g_s1>>>(out4 + 0 * HALF_VEC4);   // W tokens [0,2048)
    cudaEventRecord(g_ev[0], g_s1);
    fill_cs_kernel<<<4096, 256, 0, g_s1>>>(out4 + 1 * HALF_VEC4);   // W tokens [2048,4096)
    cudaEventRecord(g_ev[1], g_s1);
    fill_cs_kernel<<<4096, 256, 0, g_s1>>>(out4 + 2 * HALF_VEC4);   // M tokens [0,2048)
    cudaEventRecord(g_ev[2], g_s1);
    fill_cs_kernel<<<4096, 256, 0, g_s1>>>(out4 + 3 * HALF_VEC4);   // M tokens [2048,4096)
    cudaEventRecord(g_ev[3], g_s1);

    // Main chain.
    logits_top2_kernel<<<512, 256>>>(x, w, out);
    rank_slot_kernel<<<NEXP, 1024>>>();
    gather_kernel<<<NSLOT, 256>>>(x, out);

    // Pipelined sparse scatters: each waits only on its own zeroed chunk.
    cudaStreamWaitEvent(0, g_ev[0], 0);
    scatter_w_kernel<<<16, 256>>>(out, 0);
    cudaStreamWaitEvent(0, g_ev[1], 0);
    scatter_w_kernel<<<16, 256>>>(out, 2048);
    cudaStreamWaitEvent(0, g_ev[2], 0);
    scatter_m_kernel<<<16, 256>>>(out, 0);
    cudaStreamWaitEvent(0, g_ev[3], 0);
    scatter_m_kernel<<<16, 256>>>(out, 2048);
}